// round 2
// baseline (speedup 1.0000x reference)
#include <cuda_runtime.h>

#define NB    32          // batch
#define NT    24          // time steps
#define SZ    768         // size
#define NS    6           // k-slabs per (b,t)
#define SLAB  128         // SZ / NS  (columns per slab)
#define NTHR  256
#define NWARP 8

// relu(y_t) carry produced at step t, consumed at step t+1. t = 0..NT-2 used.
__device__ float g_carry[NT][NB][SZ];
// completion counters: g_done[t][b] counts finished slabs of (t,b)
__device__ int g_done[NT][NB];

__global__ void init_flags_kernel() {
    int idx = threadIdx.x;                // 768 threads = NT*NB
    ((int*)g_done)[idx] = 0;
}

__global__ void __launch_bounds__(NTHR, 4)
scan_kernel(const float* __restrict__ inp,
            const float* __restrict__ param,
            float* __restrict__ out)
{
    __shared__ float s_y[SZ];
    __shared__ float s_red[NWARP][SLAB];

    const int s    = blockIdx.x;          // slab id 0..NS-1
    const int b    = blockIdx.y;          // batch  0..NB-1
    const int tid  = threadIdx.x;
    const int w    = tid >> 5;
    const int lane = tid & 31;
    const int kbase = s * SLAB;

    for (int t = 0; t < NT; ++t) {
        // ---- wait for batch b's previous step to be fully produced ----
        if (t > 0) {
            if (tid == 0) {
                while (atomicAdd(&g_done[t - 1][b], 0) < NS)
                    __nanosleep(64);
                __threadfence();          // acquire
            }
            __syncthreads();
        }

        // ---- load carry vector (768 floats) into smem ----
        if (t == 0) {
            for (int i = tid; i < SZ; i += NTHR)
                s_y[i] = __ldg(&param[i]) + 1.0f;
        } else {
            for (int i = tid; i < SZ; i += NTHR)
                s_y[i] = __ldcg(&g_carry[t - 1][b][i]);   // L2 read (coherent)
        }
        __syncthreads();

        // ---- streaming vec-mat over this k-slab ----
        // mat row i, this slab: 32 float4 = 512B contiguous, one per lane.
        const float4* mat = (const float4*)(inp + ((size_t)b * NT + t) * SZ * SZ + kbase);
        float4 acc = make_float4(0.f, 0.f, 0.f, 0.f);
        #pragma unroll 4
        for (int i = w; i < SZ; i += NWARP) {
            float4 m = __ldcs(&mat[(size_t)i * (SZ / 4) + lane]);  // evict-first stream
            float yv = s_y[i];
            acc.x = fmaf(yv, m.x, acc.x);
            acc.y = fmaf(yv, m.y, acc.y);
            acc.z = fmaf(yv, m.z, acc.z);
            acc.w = fmaf(yv, m.w, acc.w);
        }

        // ---- cross-warp reduction ----
        ((float4*)s_red[w])[lane] = acc;
        __syncthreads();

        if (tid < SLAB) {
            float sum = 0.f;
            #pragma unroll
            for (int ww = 0; ww < NWARP; ++ww) sum += s_red[ww][tid];
            const int k = kbase + tid;
            if (t == NT - 1) {
                out[b * SZ + k] = sum;                    // pre-ReLU last step
            } else {
                g_carry[t][b][k] = fmaxf(sum, 0.0f);      // ReLU carry
            }
        }

        // ---- release: make carry visible, bump the counter ----
        __threadfence();                  // order this thread's carry stores
        __syncthreads();                  // all threads' stores fenced before flag
        if (t < NT - 1 && tid == 0) {
            atomicAdd(&g_done[t][b], 1);
        }
    }
}

extern "C" void kernel_launch(void* const* d_in, const int* in_sizes, int n_in,
                              void* d_out, int out_size)
{
    const float* inp   = (const float*)d_in[0];   // [32,24,768,768] f32
    const float* param = (const float*)d_in[1];   // [768] f32
    float* out         = (float*)d_out;           // [32,768] f32

    init_flags_kernel<<<1, NT * NB>>>();
    dim3 grid(NS, NB);
    scan_kernel<<<grid, NTHR>>>(inp, param, out);
}

// round 4
// speedup vs baseline: 1.6728x; 1.6728x over previous
#include <cuda_runtime.h>

#define NB    32          // batch
#define NT    24          // time steps
#define SZ    768         // size
#define NS    6           // k-slabs per (b,t)
#define SLAB  128         // SZ / NS  (columns per slab)
#define NTHR  512
#define NWARP 16
#define RPW   (SZ / NWARP)   // rows per warp = 48
#define PRE   8              // rows prefetched across the sync point

// relu(y_t) carry produced at step t, consumed at step t+1.
__device__ float g_carry[NT][NB][SZ];
// completion counters: g_done[t][b] counts finished slabs of (t,b)
__device__ int g_done[NT][NB];

__global__ void init_flags_kernel() {
    ((int*)g_done)[threadIdx.x] = 0;      // 768 threads = NT*NB
}

__global__ void __launch_bounds__(NTHR)
scan_kernel(const float* __restrict__ inp,
            const float* __restrict__ param,
            float* __restrict__ out)
{
    __shared__ float s_y[SZ];
    __shared__ float s_red[NWARP][SLAB];

    const int s    = blockIdx.x;          // slab id 0..NS-1
    const int b    = blockIdx.y;          // batch  0..NB-1
    const int tid  = threadIdx.x;
    const int w    = tid >> 5;
    const int lane = tid & 31;
    const int kbase = s * SLAB;

    for (int t = 0; t < NT; ++t) {
        // Matrix tile for (b, t), this slab. Row i segment = 32 float4 (512B),
        // one float4 per lane, fully coalesced. Streamed once -> evict-first.
        const float4* mat =
            (const float4*)(inp + ((size_t)b * NT + t) * SZ * SZ + kbase);

        // ---- PREFETCH: issue first PRE rows' loads BEFORE the carry wait ----
        // These addresses don't depend on the carry, so they fill the sync
        // bubble with useful DRAM traffic.
        float4 m[PRE];
        #pragma unroll
        for (int u = 0; u < PRE; ++u)
            m[u] = __ldcs(&mat[(size_t)(w + NWARP * u) * (SZ / 4) + lane]);

        // ---- wait for batch b's previous step, then load carry into smem ----
        if (t > 0) {
            if (tid == 0) {
                while (atomicAdd(&g_done[t - 1][b], 0) < NS)
                    __nanosleep(32);
                __threadfence();          // acquire
            }
            __syncthreads();
            for (int i = tid; i < SZ; i += NTHR)
                s_y[i] = __ldcg(&g_carry[t - 1][b][i]);   // L2-coherent read
        } else {
            for (int i = tid; i < SZ; i += NTHR)
                s_y[i] = param[i] + 1.0f;
        }
        __syncthreads();

        // ---- compute: prefetched rows first, then stream the rest ----
        float4 acc = make_float4(0.f, 0.f, 0.f, 0.f);
        #pragma unroll
        for (int u = 0; u < PRE; ++u) {
            float yv = s_y[w + NWARP * u];
            acc.x = fmaf(yv, m[u].x, acc.x);
            acc.y = fmaf(yv, m[u].y, acc.y);
            acc.z = fmaf(yv, m[u].z, acc.z);
            acc.w = fmaf(yv, m[u].w, acc.w);
        }
        #pragma unroll
        for (int j = PRE; j < RPW; ++j) {   // fully unrolled: ptxas front-batches
            float4 mm = __ldcs(&mat[(size_t)(w + NWARP * j) * (SZ / 4) + lane]);
            float yv  = s_y[w + NWARP * j];
            acc.x = fmaf(yv, mm.x, acc.x);
            acc.y = fmaf(yv, mm.y, acc.y);
            acc.z = fmaf(yv, mm.z, acc.z);
            acc.w = fmaf(yv, mm.w, acc.w);
        }

        // ---- cross-warp reduction ----
        ((float4*)s_red[w])[lane] = acc;
        __syncthreads();

        if (tid < SLAB) {
            float sum = 0.f;
            #pragma unroll
            for (int ww = 0; ww < NWARP; ++ww) sum += s_red[ww][tid];
            const int k = kbase + tid;
            if (t == NT - 1) {
                out[b * SZ + k] = sum;                    // pre-ReLU last step
            } else {
                g_carry[t][b][k] = fmaxf(sum, 0.0f);      // ReLU carry
            }
            __threadfence();              // release: only writers need to fence
        }
        __syncthreads();                  // all writers fenced before flag
        if (t < NT - 1 && tid == 0) {
            atomicAdd(&g_done[t][b], 1);
        }
    }
}

extern "C" void kernel_launch(void* const* d_in, const int* in_sizes, int n_in,
                              void* d_out, int out_size)
{
    const float* inp   = (const float*)d_in[0];   // [32,24,768,768] f32
    const float* param = (const float*)d_in[1];   // [768] f32
    float* out         = (float*)d_out;           // [32,768] f32

    init_flags_kernel<<<1, NT * NB>>>();
    dim3 grid(NS, NB);
    scan_kernel<<<grid, NTHR>>>(inp, param, out);
}

// round 6
// speedup vs baseline: 1.6859x; 1.0079x over previous
#include <cuda_runtime.h>
#include <cstdint>

#define NB    32          // batch
#define NT    24          // time steps
#define SZ    768         // size
#define NS    6           // k-slabs per (b,t)
#define SLAB  128         // SZ / NS  (columns per slab)
#define NTHR  512
#define NWARP 16
#define RPW   (SZ / NWARP)   // rows per warp = 48
#define PRE   8              // register-prefetch rows per warp: j = 0..7
#define SMJ0  8              // smem-prefetch rows per warp: j = 8..11
#define SMJ1  12
#define SMROWS ((SMJ1 - SMJ0) * NWARP)   // 64 global rows (128..191)
#define SMCHUNKS (SMROWS * 32)           // 2048 x 16B = 32KB
#define CPT   (SMCHUNKS / NTHR)          // 4 cp.async per thread

// relu(y_t) carry produced at step t, consumed at step t+1.
__device__ float g_carry[NT][NB][SZ];
// completion counters: g_done[t][b] counts finished slabs of (t,b)
__device__ int g_done[NT][NB];

__global__ void init_flags_kernel() {
    ((int*)g_done)[threadIdx.x] = 0;      // 768 threads = NT*NB
}

__device__ __forceinline__ void cp_async16(uint32_t saddr, const void* gaddr) {
    asm volatile("cp.async.cg.shared.global [%0], [%1], 16;\n"
                 :: "r"(saddr), "l"(gaddr));
}

__global__ void __launch_bounds__(NTHR, 2)   // force regs<=64: 2 blocks/SM co-residency
scan_kernel(const float* __restrict__ inp,
            const float* __restrict__ param,
            float* __restrict__ out)
{
    __shared__ float  s_y[SZ];                       // 3 KB
    __shared__ float  s_red[NWARP][SLAB];            // 8 KB
    __shared__ float4 s_mat[SMROWS * 32];            // 32 KB: rows 128..191 linear

    const int s    = blockIdx.x;          // slab id 0..NS-1
    const int b    = blockIdx.y;          // batch  0..NB-1
    const int tid  = threadIdx.x;
    const int w    = tid >> 5;
    const int lane = tid & 31;
    const int kbase = s * SLAB;

    const uint32_t s_mat_base = (uint32_t)__cvta_generic_to_shared(s_mat);

    for (int t = 0; t < NT; ++t) {
        // Matrix tile for (b, t), this slab. Row i segment = 32 float4 (512B),
        // one float4 per lane, fully coalesced, streamed once.
        const float4* mat =
            (const float4*)(inp + ((size_t)b * NT + t) * SZ * SZ + kbase);

        // ---- PREFETCH ACROSS THE SYNC (no carry dependency) ----
        // (a) registers: rows j=0..7 for this warp
        float4 m[PRE];
        #pragma unroll
        for (int u = 0; u < PRE; ++u)
            m[u] = __ldcs(&mat[(size_t)(w + NWARP * u) * (SZ / 4) + lane]);

        // (b) cp.async -> smem: global rows 128..191 (j=8..11 for every warp),
        //     32KB, zero register cost. Chunk c (16B) = linear offset 16*c.
        #pragma unroll
        for (int k = 0; k < CPT; ++k) {
            int c   = tid + NTHR * k;                 // 0..2047
            int row = (SMJ0 * NWARP) + (c >> 5);      // 128 + c/32
            int ln  = c & 31;
            cp_async16(s_mat_base + (uint32_t)c * 16,
                       &mat[(size_t)row * (SZ / 4) + ln]);
        }
        asm volatile("cp.async.commit_group;\n" ::: "memory");

        // ---- wait for batch b's previous step, then load carry into smem ----
        if (t > 0) {
            if (tid == 0) {
                while (atomicAdd(&g_done[t - 1][b], 0) < NS)
                    __nanosleep(32);
                __threadfence();          // acquire
            }
            __syncthreads();
            for (int i = tid; i < SZ; i += NTHR)
                s_y[i] = __ldcg(&g_carry[t - 1][b][i]);   // L2-coherent read
        } else {
            for (int i = tid; i < SZ; i += NTHR)
                s_y[i] = param[i] + 1.0f;
        }
        asm volatile("cp.async.wait_group 0;\n" ::: "memory");
        __syncthreads();

        // ---- compute ----
        float4 acc = make_float4(0.f, 0.f, 0.f, 0.f);
        // (a) register-prefetched rows
        #pragma unroll
        for (int u = 0; u < PRE; ++u) {
            float yv = s_y[w + NWARP * u];
            acc.x = fmaf(yv, m[u].x, acc.x);
            acc.y = fmaf(yv, m[u].y, acc.y);
            acc.z = fmaf(yv, m[u].z, acc.z);
            acc.w = fmaf(yv, m[u].w, acc.w);
        }
        // (b) smem-prefetched rows j=8..11 (row = w+16j, q = row-128)
        #pragma unroll
        for (int j = SMJ0; j < SMJ1; ++j) {
            int row = w + NWARP * j;
            float4 mm = s_mat[(row - SMJ0 * NWARP) * 32 + lane];
            float yv  = s_y[row];
            acc.x = fmaf(yv, mm.x, acc.x);
            acc.y = fmaf(yv, mm.y, acc.y);
            acc.z = fmaf(yv, mm.z, acc.z);
            acc.w = fmaf(yv, mm.w, acc.w);
        }
        // (c) streamed remainder j=12..47
        #pragma unroll
        for (int j = SMJ1; j < RPW; ++j) {
            float4 mm = __ldcs(&mat[(size_t)(w + NWARP * j) * (SZ / 4) + lane]);
            float yv  = s_y[w + NWARP * j];
            acc.x = fmaf(yv, mm.x, acc.x);
            acc.y = fmaf(yv, mm.y, acc.y);
            acc.z = fmaf(yv, mm.z, acc.z);
            acc.w = fmaf(yv, mm.w, acc.w);
        }

        // ---- cross-warp reduction ----
        ((float4*)s_red[w])[lane] = acc;
        __syncthreads();

        if (tid < SLAB) {
            float sum = 0.f;
            #pragma unroll
            for (int ww = 0; ww < NWARP; ++ww) sum += s_red[ww][tid];
            const int k = kbase + tid;
            if (t == NT - 1) {
                out[b * SZ + k] = sum;                    // pre-ReLU last step
            } else {
                g_carry[t][b][k] = fmaxf(sum, 0.0f);      // ReLU carry
            }
            __threadfence();              // release: only writers fence
        }
        __syncthreads();                  // all writers fenced before flag
        if (t < NT - 1 && tid == 0) {
            atomicAdd(&g_done[t][b], 1);
        }
    }
}

extern "C" void kernel_launch(void* const* d_in, const int* in_sizes, int n_in,
                              void* d_out, int out_size)
{
    const float* inp   = (const float*)d_in[0];   // [32,24,768,768] f32
    const float* param = (const float*)d_in[1];   // [768] f32
    float* out         = (float*)d_out;           // [32,768] f32

    init_flags_kernel<<<1, NT * NB>>>();
    dim3 grid(NS, NB);
    scan_kernel<<<grid, NTHR>>>(inp, param, out);
}